// round 1
// baseline (speedup 1.0000x reference)
#include <cuda_runtime.h>
#include <cuda_bf16.h>

#define BI 4
#define CI 64
#define HI 128
#define WI 128
#define HWI (HI*WI)
#define JO 18
#define CO 64
#define KKN 9

// Scratch for offset field: layout [b][j][h][w], j = 2*kk + {0:dy, 1:dx}
__device__ float g_off[BI*JO*HWI];

// ---------------------------------------------------------------------------
// Kernel 1: offset conv  off[b,j,h,w] = b_off[j] + sum_{c,ky,kx} x[b,c,h-1+ky,w-1+kx]*w_off[j,c,ky,kx]
// Thread handles 2 pixels; weights transposed in smem as [tap][c][j].
// ---------------------------------------------------------------------------
__global__ void offset_conv_kernel(const float* __restrict__ x,
                                   const float* __restrict__ w_off,
                                   const float* __restrict__ b_off) {
    __shared__ float ws[KKN*CI*JO];   // 10368 floats = 41.5 KB
    int tid = threadIdx.x;
    for (int i = tid; i < KKN*CI*JO; i += blockDim.x) {
        int j = i % JO; int rest = i / JO; int c = rest % CI; int tap = rest / CI;
        ws[i] = w_off[(j*CI + c)*KKN + tap];
    }
    __syncthreads();

    int p0 = blockIdx.x * (2*blockDim.x) + tid;
    int p1 = p0 + blockDim.x;

    float acc0[JO], acc1[JO];
    #pragma unroll
    for (int j = 0; j < JO; j++) { float bo = __ldg(&b_off[j]); acc0[j] = bo; acc1[j] = bo; }

    int b0 = p0 >> 14, rem0 = p0 & (HWI-1), h0 = rem0 >> 7, w0 = rem0 & (WI-1);
    int b1 = p1 >> 14, rem1 = p1 & (HWI-1), h1 = rem1 >> 7, w1 = rem1 & (WI-1);
    const float* xb0 = x + b0*CI*HWI;
    const float* xb1 = x + b1*CI*HWI;

    for (int tap = 0; tap < KKN; tap++) {
        int ky = tap / 3, kx = tap % 3;
        int y0 = h0 - 1 + ky, xx0 = w0 - 1 + kx;
        int y1 = h1 - 1 + ky, xx1 = w1 - 1 + kx;
        bool v0 = (y0 >= 0) & (y0 < HI) & (xx0 >= 0) & (xx0 < WI);
        bool v1 = (y1 >= 0) & (y1 < HI) & (xx1 >= 0) & (xx1 < WI);
        int i0 = y0*WI + xx0, i1 = y1*WI + xx1;
        for (int c = 0; c < CI; c++) {
            float a  = v0 ? __ldg(xb0 + c*HWI + i0) : 0.f;
            float bv = v1 ? __ldg(xb1 + c*HWI + i1) : 0.f;
            const float2* w2 = (const float2*)(ws + (tap*CI + c)*JO);
            #pragma unroll
            for (int q = 0; q < 9; q++) {
                float2 wv = w2[q];
                acc0[2*q+0] += a  * wv.x;
                acc0[2*q+1] += a  * wv.y;
                acc1[2*q+0] += bv * wv.x;
                acc1[2*q+1] += bv * wv.y;
            }
        }
    }
    #pragma unroll
    for (int j = 0; j < JO; j++) {
        g_off[(b0*JO + j)*HWI + rem0] = acc0[j];
        g_off[(b1*JO + j)*HWI + rem1] = acc1[j];
    }
}

// ---------------------------------------------------------------------------
// Kernel 2: deformable sampling + projection.
// Thread per pixel, acc[64] in registers.
// w_def transposed in smem as [c][kk][o] (o contiguous -> broadcast float4 LDS).
// ---------------------------------------------------------------------------
__global__ void deform_main_kernel(const float* __restrict__ x,
                                   const float* __restrict__ w_def,
                                   float* __restrict__ out) {
    extern __shared__ float wt[];  // CI*KKN*CO = 36864 floats = 147456 B
    int tid = threadIdx.x;
    for (int i = tid; i < CI*KKN*CO; i += blockDim.x) {
        int o = i & 63; int rest = i >> 6; int kk = rest % KKN; int c = rest / KKN;
        wt[i] = w_def[(o*CI + c)*KKN + kk];
    }
    __syncthreads();

    int p = blockIdx.x * blockDim.x + tid;
    int b = p >> 14, rem = p & (HWI-1);
    int h = rem >> 7, w = rem & (WI-1);
    const float* xb = x + b*CI*HWI;
    const float* offp = g_off + b*JO*HWI + rem;

    float acc[CO];
    #pragma unroll
    for (int o = 0; o < CO; o++) acc[o] = 0.f;

    for (int kk = 0; kk < KKN; kk++) {
        float dy = __ldg(offp + (2*kk + 0)*HWI);
        float dx = __ldg(offp + (2*kk + 1)*HWI);
        float py = (float)(h - 1 + kk / 3) + dy;
        float px = (float)(w - 1 + kk % 3) + dx;
        float y0f = floorf(py), x0f = floorf(px);
        float fy = py - y0f, fx = px - x0f;
        int y0 = (int)y0f, x0 = (int)x0f;
        int y1 = y0 + 1,   x1 = x0 + 1;
        float vy0 = (y0 >= 0 && y0 < HI) ? 1.f : 0.f;
        float vy1 = (y1 >= 0 && y1 < HI) ? 1.f : 0.f;
        float vx0 = (x0 >= 0 && x0 < WI) ? 1.f : 0.f;
        float vx1 = (x1 >= 0 && x1 < WI) ? 1.f : 0.f;
        float w00 = (1.f - fy) * (1.f - fx) * vy0 * vx0;
        float w01 = (1.f - fy) * fx        * vy0 * vx1;
        float w10 = fy         * (1.f - fx) * vy1 * vx0;
        float w11 = fy         * fx        * vy1 * vx1;
        int y0c = min(max(y0, 0), HI-1), y1c = min(max(y1, 0), HI-1);
        int x0c = min(max(x0, 0), WI-1), x1c = min(max(x1, 0), WI-1);
        int i00 = y0c*WI + x0c, i01 = y0c*WI + x1c;
        int i10 = y1c*WI + x0c, i11 = y1c*WI + x1c;

        const float* wkk = wt + kk*CO;
        #pragma unroll 2
        for (int c = 0; c < CI; c++) {
            const float* xc = xb + c*HWI;
            float s = w00*__ldg(xc + i00) + w01*__ldg(xc + i01)
                    + w10*__ldg(xc + i10) + w11*__ldg(xc + i11);
            const float4* w4 = (const float4*)(wkk + c*(KKN*CO));
            #pragma unroll
            for (int q = 0; q < 16; q++) {
                float4 wv = w4[q];
                acc[4*q+0] += s * wv.x;
                acc[4*q+1] += s * wv.y;
                acc[4*q+2] += s * wv.z;
                acc[4*q+3] += s * wv.w;
            }
        }
    }

    #pragma unroll
    for (int o = 0; o < CO; o++)
        out[(b*CO + o)*HWI + rem] = acc[o];
}

// ---------------------------------------------------------------------------
// Launch
// Inputs (metadata order): x (4*64*128*128), w_off (18*64*9), b_off (18), w_def (64*64*9)
// Output: (4, 64, 128, 128) fp32
// ---------------------------------------------------------------------------
extern "C" void kernel_launch(void* const* d_in, const int* in_sizes, int n_in,
                              void* d_out, int out_size) {
    const float* x     = (const float*)d_in[0];
    const float* w_off = (const float*)d_in[1];
    const float* b_off = (const float*)d_in[2];
    const float* w_def = (const float*)d_in[3];
    float* out = (float*)d_out;

    const int total_px = BI*HWI;             // 65536
    const int smem_main = CI*KKN*CO*4;       // 147456 bytes

    cudaFuncSetAttribute(deform_main_kernel,
                         cudaFuncAttributeMaxDynamicSharedMemorySize, smem_main);

    offset_conv_kernel<<<total_px/(2*256), 256>>>(x, w_off, b_off);
    deform_main_kernel<<<total_px/256, 256, smem_main>>>(x, w_def, out);
}

// round 4
// speedup vs baseline: 1.2313x; 1.2313x over previous
#include <cuda_runtime.h>
#include <cuda_bf16.h>

#define BI 4
#define CI 64
#define HI 128
#define WI 128
#define HWI (HI*WI)
#define JO 18
#define JP 20
#define CO 64
#define KKN 9

typedef unsigned long long u64;

__device__ __forceinline__ void ffma2(u64 &d, u64 a, u64 b) {
    asm("fma.rn.f32x2 %0, %1, %2, %0;" : "+l"(d) : "l"(a), "l"(b));
}
__device__ __forceinline__ u64 pack2(float lo, float hi) {
    u64 r; asm("mov.b64 %0, {%1, %2};" : "=l"(r) : "f"(lo), "f"(hi)); return r;
}
__device__ __forceinline__ float2 unpack2(u64 v) {
    float2 r; asm("mov.b64 {%0, %1}, %2;" : "=f"(r.x), "=f"(r.y) : "l"(v)); return r;
}

// Scratch for offset field: layout [b][j][h][w], j = 2*kk + {0:dy, 1:dx}
__device__ float g_off[BI*JO*HWI];

// ---------------------------------------------------------------------------
// Kernel 1: offset conv, 1 pixel/thread, packed f32x2 accumulators.
// Weights in smem as [tap][c][j] with row padded to 20 floats (80 B, 16B-aligned).
// ---------------------------------------------------------------------------
__global__ __launch_bounds__(256, 4)
void offset_conv_kernel(const float* __restrict__ x,
                        const float* __restrict__ w_off,
                        const float* __restrict__ b_off) {
    __shared__ __align__(16) float ws[KKN*CI*JP];   // 46080 B
    int tid = threadIdx.x;
    for (int i = tid; i < KKN*CI*JO; i += blockDim.x) {
        int j = i % JO; int rest = i / JO; int c = rest % CI; int tap = rest / CI;
        ws[(tap*CI + c)*JP + j] = w_off[(j*CI + c)*KKN + tap];
    }
    __syncthreads();

    int p = blockIdx.x * blockDim.x + tid;
    int b = p >> 14, rem = p & (HWI-1);
    int h = rem >> 7, w = rem & (WI-1);
    const float* xb = x + b*CI*HWI;

    u64 acc[9];
    #pragma unroll
    for (int q = 0; q < 9; q++)
        acc[q] = pack2(__ldg(&b_off[2*q]), __ldg(&b_off[2*q+1]));

    for (int tap = 0; tap < KKN; tap++) {
        int ky = tap / 3, kx = tap % 3;
        int y = h - 1 + ky, xx = w - 1 + kx;
        bool v = (y >= 0) & (y < HI) & (xx >= 0) & (xx < WI);
        int idx = y*WI + xx;
        const float* wrow = ws + tap*CI*JP;
        for (int c = 0; c < CI; c++) {
            float a = v ? __ldg(xb + c*HWI + idx) : 0.f;
            u64 a2 = pack2(a, a);
            const ulonglong2* w4 = (const ulonglong2*)(wrow + c*JP);
            #pragma unroll
            for (int q = 0; q < 4; q++) {
                ulonglong2 wv = w4[q];
                ffma2(acc[2*q+0], a2, wv.x);
                ffma2(acc[2*q+1], a2, wv.y);
            }
            u64 w8 = *(const u64*)(wrow + c*JP + 16);
            ffma2(acc[8], a2, w8);
        }
    }
    #pragma unroll
    for (int q = 0; q < 9; q++) {
        float2 vv = unpack2(acc[q]);
        g_off[(b*JO + 2*q+0)*HWI + rem] = vv.x;
        g_off[(b*JO + 2*q+1)*HWI + rem] = vv.y;
    }
}

// ---------------------------------------------------------------------------
// Kernel 2: deformable sampling + projection.
// 1 pixel/thread, packed f32x2 accumulators (32 x u64).
// Weight smem tiled per-tap: 16 KB [c][o], reloaded each kk -> 4 CTAs/SM.
// ---------------------------------------------------------------------------
__global__ __launch_bounds__(128, 4)
void deform_main_kernel(const float* __restrict__ x,
                        const float* __restrict__ w_def,
                        float* __restrict__ out) {
    __shared__ __align__(16) float wt[CI*CO];  // 16384 B, one tap at a time
    int tid = threadIdx.x;
    int p = blockIdx.x * blockDim.x + tid;
    int b = p >> 14, rem = p & (HWI-1);
    int h = rem >> 7, w = rem & (WI-1);
    const float* xb = x + b*CI*HWI;
    const float* offp = g_off + b*JO*HWI + rem;

    u64 acc[CO/2];
    #pragma unroll
    for (int q = 0; q < CO/2; q++) acc[q] = 0ULL;

    for (int kk = 0; kk < KKN; kk++) {
        __syncthreads();
        for (int i = tid; i < CI*CO; i += blockDim.x) {
            int o = i & 63, c = i >> 6;
            wt[i] = w_def[(o*CI + c)*KKN + kk];
        }
        __syncthreads();

        float dy = __ldg(offp + (2*kk + 0)*HWI);
        float dx = __ldg(offp + (2*kk + 1)*HWI);
        float py = (float)(h - 1 + kk / 3) + dy;
        float px = (float)(w - 1 + kk % 3) + dx;
        float y0f = floorf(py), x0f = floorf(px);
        float fy = py - y0f, fx = px - x0f;
        int y0 = (int)y0f, x0 = (int)x0f;
        int y1 = y0 + 1,   x1 = x0 + 1;
        float vy0 = (y0 >= 0 && y0 < HI) ? 1.f : 0.f;
        float vy1 = (y1 >= 0 && y1 < HI) ? 1.f : 0.f;
        float vx0 = (x0 >= 0 && x0 < WI) ? 1.f : 0.f;
        float vx1 = (x1 >= 0 && x1 < WI) ? 1.f : 0.f;
        float w00 = (1.f - fy) * (1.f - fx) * vy0 * vx0;
        float w01 = (1.f - fy) * fx         * vy0 * vx1;
        float w10 = fy         * (1.f - fx) * vy1 * vx0;
        float w11 = fy         * fx         * vy1 * vx1;
        int y0c = min(max(y0, 0), HI-1), y1c = min(max(y1, 0), HI-1);
        int x0c = min(max(x0, 0), WI-1), x1c = min(max(x1, 0), WI-1);
        int i00 = y0c*WI + x0c, i01 = y0c*WI + x1c;
        int i10 = y1c*WI + x0c, i11 = y1c*WI + x1c;

        for (int c = 0; c < CI; c++) {
            const float* xc = xb + c*HWI;
            float s = w00*__ldg(xc + i00) + w01*__ldg(xc + i01)
                    + w10*__ldg(xc + i10) + w11*__ldg(xc + i11);
            u64 s2 = pack2(s, s);
            const ulonglong2* w4 = (const ulonglong2*)(wt + (c << 6));
            #pragma unroll
            for (int q = 0; q < 16; q++) {
                ulonglong2 wv = w4[q];
                ffma2(acc[2*q+0], s2, wv.x);
                ffma2(acc[2*q+1], s2, wv.y);
            }
        }
    }

    #pragma unroll
    for (int q = 0; q < CO/2; q++) {
        float2 vv = unpack2(acc[q]);
        out[(b*CO + 2*q+0)*HWI + rem] = vv.x;
        out[(b*CO + 2*q+1)*HWI + rem] = vv.y;
    }
}

// ---------------------------------------------------------------------------
// Launch
// Inputs (metadata order): x (4*64*128*128), w_off (18*64*9), b_off (18), w_def (64*64*9)
// Output: (4, 64, 128, 128) fp32
// ---------------------------------------------------------------------------
extern "C" void kernel_launch(void* const* d_in, const int* in_sizes, int n_in,
                              void* d_out, int out_size) {
    const float* x     = (const float*)d_in[0];
    const float* w_off = (const float*)d_in[1];
    const float* b_off = (const float*)d_in[2];
    const float* w_def = (const float*)d_in[3];
    float* out = (float*)d_out;

    const int total_px = BI*HWI;  // 65536

    offset_conv_kernel<<<total_px/256, 256>>>(x, w_off, b_off);
    deform_main_kernel<<<total_px/128, 128>>>(x, w_def, out);
}

// round 5
// speedup vs baseline: 1.5607x; 1.2675x over previous
#include <cuda_runtime.h>
#include <cuda_bf16.h>

#define BI 4
#define CI 64
#define HI 128
#define WI 128
#define HWI (HI*WI)
#define JO 18
#define JP 20
#define CO 64
#define KKN 9
#define TPX 128

typedef unsigned long long u64;

__device__ __forceinline__ void ffma2(u64 &d, u64 a, u64 b) {
    asm("fma.rn.f32x2 %0, %1, %2, %0;" : "+l"(d) : "l"(a), "l"(b));
}
__device__ __forceinline__ u64 pack2(float lo, float hi) {
    u64 r; asm("mov.b64 %0, {%1, %2};" : "=l"(r) : "f"(lo), "f"(hi)); return r;
}
__device__ __forceinline__ float2 unpack2(u64 v) {
    float2 r; asm("mov.b64 {%0, %1}, %2;" : "=f"(r.x), "=f"(r.y) : "l"(v)); return r;
}

// Scratch for offset field: layout [b][j][h][w], j = 2*kk + {0:dy, 1:dx}
__device__ float g_off[BI*JO*HWI];

// ---------------------------------------------------------------------------
// Kernel 1: offset conv, 1 pixel/thread, packed f32x2 accumulators.
// ---------------------------------------------------------------------------
__global__ __launch_bounds__(256, 4)
void offset_conv_kernel(const float* __restrict__ x,
                        const float* __restrict__ w_off,
                        const float* __restrict__ b_off) {
    __shared__ __align__(16) float ws[KKN*CI*JP];
    int tid = threadIdx.x;
    for (int i = tid; i < KKN*CI*JO; i += blockDim.x) {
        int j = i % JO; int rest = i / JO; int c = rest % CI; int tap = rest / CI;
        ws[(tap*CI + c)*JP + j] = w_off[(j*CI + c)*KKN + tap];
    }
    __syncthreads();

    int p = blockIdx.x * blockDim.x + tid;
    int b = p >> 14, rem = p & (HWI-1);
    int h = rem >> 7, w = rem & (WI-1);
    const float* xb = x + b*CI*HWI;

    u64 acc[9];
    #pragma unroll
    for (int q = 0; q < 9; q++)
        acc[q] = pack2(__ldg(&b_off[2*q]), __ldg(&b_off[2*q+1]));

    for (int tap = 0; tap < KKN; tap++) {
        int ky = tap / 3, kx = tap % 3;
        int y = h - 1 + ky, xx = w - 1 + kx;
        bool v = (y >= 0) & (y < HI) & (xx >= 0) & (xx < WI);
        int idx = y*WI + xx;
        const float* wrow = ws + tap*CI*JP;
        for (int c = 0; c < CI; c++) {
            float a = v ? __ldg(xb + c*HWI + idx) : 0.f;
            u64 a2 = pack2(a, a);
            const ulonglong2* w4 = (const ulonglong2*)(wrow + c*JP);
            #pragma unroll
            for (int q = 0; q < 4; q++) {
                ulonglong2 wv = w4[q];
                ffma2(acc[2*q+0], a2, wv.x);
                ffma2(acc[2*q+1], a2, wv.y);
            }
            u64 w8 = *(const u64*)(wrow + c*JP + 16);
            ffma2(acc[8], a2, w8);
        }
    }
    #pragma unroll
    for (int q = 0; q < 9; q++) {
        float2 vv = unpack2(acc[q]);
        g_off[(b*JO + 2*q+0)*HWI + rem] = vv.x;
        g_off[(b*JO + 2*q+1)*HWI + rem] = vv.y;
    }
}

// ---------------------------------------------------------------------------
// Kernel 2: per-tap im2col into smem + register-blocked GEMM.
// Block = 128 threads = one image row (128 px).
// Phase 1: thread samples its own pixel for all 64 c -> S[c][128].
// Phase 2: 8o x 8px register tile per thread; px owned as pairs
//          {2*(tid&15)+32j, +1} j=0..3 -> conflict-free LDS.64 sample reads,
//          broadcast LDS.128 weight reads, coalesced STG.64 stores.
// ---------------------------------------------------------------------------
__global__ __launch_bounds__(128, 4)
void deform_main_kernel(const float* __restrict__ x,
                        const float* __restrict__ w_def,
                        float* __restrict__ out) {
    extern __shared__ __align__(16) float sm[];
    float* wt = sm;            // [c][o]  64*64 = 16 KB
    float* S  = sm + CI*CO;    // [c][px] 64*128 = 32 KB

    int tid = threadIdx.x;
    int blk = blockIdx.x;
    int b = blk >> 7;          // 128 rows per image
    int h = blk & 127;
    int rowoff = h * WI;
    const float* xb = x + b*CI*HWI;

    // sampler: this thread's pixel is (h, tid)
    int w = tid;
    const float* offp = g_off + b*JO*HWI + rowoff + w;

    // GEMM tile mapping
    int o0 = (tid >> 4) * 8;   // 8 output channels
    int pb = tid & 15;         // pair-column base

    u64 acc[8][4];
    #pragma unroll
    for (int o = 0; o < 8; o++)
        #pragma unroll
        for (int j = 0; j < 4; j++) acc[o][j] = 0ULL;

    for (int kk = 0; kk < KKN; kk++) {
        __syncthreads();   // previous GEMM done reading wt/S

        // stage weight tap [c][o]
        for (int i = tid; i < CI*CO; i += TPX) {
            int o = i & 63, c = i >> 6;
            wt[i] = __ldg(&w_def[(o*CI + c)*KKN + kk]);
        }

        // bilinear setup for own pixel
        float dy = __ldg(offp + (2*kk + 0)*HWI);
        float dx = __ldg(offp + (2*kk + 1)*HWI);
        float py = (float)(h - 1 + kk / 3) + dy;
        float px = (float)(w - 1 + kk % 3) + dx;
        float y0f = floorf(py), x0f = floorf(px);
        float fy = py - y0f, fx = px - x0f;
        int y0 = (int)y0f, x0 = (int)x0f;
        int y1 = y0 + 1,   x1 = x0 + 1;
        float vy0 = (y0 >= 0 && y0 < HI) ? 1.f : 0.f;
        float vy1 = (y1 >= 0 && y1 < HI) ? 1.f : 0.f;
        float vx0 = (x0 >= 0 && x0 < WI) ? 1.f : 0.f;
        float vx1 = (x1 >= 0 && x1 < WI) ? 1.f : 0.f;
        float w00 = (1.f - fy) * (1.f - fx) * vy0 * vx0;
        float w01 = (1.f - fy) * fx         * vy0 * vx1;
        float w10 = fy         * (1.f - fx) * vy1 * vx0;
        float w11 = fy         * fx         * vy1 * vx1;
        int y0c = min(max(y0, 0), HI-1), y1c = min(max(y1, 0), HI-1);
        int x0c = min(max(x0, 0), WI-1), x1c = min(max(x1, 0), WI-1);
        int i00 = y0c*WI + x0c, i01 = y0c*WI + x1c;
        int i10 = y1c*WI + x0c, i11 = y1c*WI + x1c;

        // sample all channels -> S[c][tid]
        #pragma unroll 4
        for (int c = 0; c < CI; c++) {
            const float* xc = xb + c*HWI;
            float s = w00*__ldg(xc + i00) + w01*__ldg(xc + i01)
                    + w10*__ldg(xc + i10) + w11*__ldg(xc + i11);
            S[c*TPX + tid] = s;
        }
        __syncthreads();

        // GEMM: acc[8o][8px] += W[o][c] * S[c][px]
        #pragma unroll 4
        for (int c = 0; c < CI; c++) {
            const float* wr = wt + (c << 6) + o0;
            float4 wa = *(const float4*)(wr);
            float4 wb = *(const float4*)(wr + 4);
            u64 w2[8];
            w2[0] = pack2(wa.x, wa.x); w2[1] = pack2(wa.y, wa.y);
            w2[2] = pack2(wa.z, wa.z); w2[3] = pack2(wa.w, wa.w);
            w2[4] = pack2(wb.x, wb.x); w2[5] = pack2(wb.y, wb.y);
            w2[6] = pack2(wb.z, wb.z); w2[7] = pack2(wb.w, wb.w);
            const u64* srow = (const u64*)(S + c*TPX);
            u64 s2[4];
            #pragma unroll
            for (int j = 0; j < 4; j++) s2[j] = srow[pb + 16*j];
            #pragma unroll
            for (int o = 0; o < 8; o++)
                #pragma unroll
                for (int j = 0; j < 4; j++)
                    ffma2(acc[o][j], s2[j], w2[o]);
        }
    }

    // write out: thread's px pairs at 2*pb + 32j
    #pragma unroll
    for (int o = 0; o < 8; o++) {
        float* orow = out + (b*CO + o0 + o)*HWI + rowoff;
        #pragma unroll
        for (int j = 0; j < 4; j++) {
            float2 v = unpack2(acc[o][j]);
            *(float2*)(orow + 2*pb + 32*j) = v;
        }
    }
}

// ---------------------------------------------------------------------------
// Launch
// Inputs: x (4*64*128*128), w_off (18*64*9), b_off (18), w_def (64*64*9)
// Output: (4, 64, 128, 128) fp32
// ---------------------------------------------------------------------------
extern "C" void kernel_launch(void* const* d_in, const int* in_sizes, int n_in,
                              void* d_out, int out_size) {
    const float* x     = (const float*)d_in[0];
    const float* w_off = (const float*)d_in[1];
    const float* b_off = (const float*)d_in[2];
    const float* w_def = (const float*)d_in[3];
    float* out = (float*)d_out;

    const int total_px = BI*HWI;                 // 65536
    const int smem_main = (CI*CO + CI*TPX) * 4;  // 49152 B

    static int configured = 0;
    if (!configured) {
        cudaFuncSetAttribute(deform_main_kernel,
                             cudaFuncAttributeMaxDynamicSharedMemorySize, smem_main);
        configured = 1;
    }

    offset_conv_kernel<<<total_px/256, 256>>>(x, w_off, b_off);
    deform_main_kernel<<<total_px/TPX, TPX, smem_main>>>(x, w_def, out);
}

// round 6
// speedup vs baseline: 1.6893x; 1.0824x over previous
#include <cuda_runtime.h>
#include <cuda_bf16.h>

#define BI 4
#define CI 64
#define HI 128
#define WI 128
#define HWI (HI*WI)
#define JO 18
#define JP 20
#define CO 64
#define KKN 9
#define TPX 128

typedef unsigned long long u64;

__device__ __forceinline__ void ffma2(u64 &d, u64 a, u64 b) {
    asm("fma.rn.f32x2 %0, %1, %2, %0;" : "+l"(d) : "l"(a), "l"(b));
}
__device__ __forceinline__ u64 pack2(float lo, float hi) {
    u64 r; asm("mov.b64 %0, {%1, %2};" : "=l"(r) : "f"(lo), "f"(hi)); return r;
}
__device__ __forceinline__ float2 unpack2(u64 v) {
    float2 r; asm("mov.b64 {%0, %1}, %2;" : "=f"(r.x), "=f"(r.y) : "l"(v)); return r;
}

// Scratch: offsets [b][j][h][w]  and transposed def-weights [kk][c][o]
__device__ float g_off[BI*JO*HWI];
__device__ float g_wt[KKN*CI*CO];

// ---------------------------------------------------------------------------
// Prep: transpose w_def [o][c][kk] -> g_wt [kk][c][o]
// ---------------------------------------------------------------------------
__global__ void transpose_wdef_kernel(const float* __restrict__ w_def) {
    int i = blockIdx.x * blockDim.x + threadIdx.x;   // i over [kk][c][o]
    if (i < KKN*CI*CO) {
        int o = i & 63; int rest = i >> 6; int c = rest % CI; int kk = rest / CI;
        g_wt[i] = w_def[(o*CI + c)*KKN + kk];
    }
}

// ---------------------------------------------------------------------------
// Kernel 1: offset conv, 1 pixel/thread, packed f32x2 accumulators.
// ---------------------------------------------------------------------------
__global__ __launch_bounds__(256, 4)
void offset_conv_kernel(const float* __restrict__ x,
                        const float* __restrict__ w_off,
                        const float* __restrict__ b_off) {
    __shared__ __align__(16) float ws[KKN*CI*JP];
    int tid = threadIdx.x;
    for (int i = tid; i < KKN*CI*JO; i += blockDim.x) {
        int j = i % JO; int rest = i / JO; int c = rest % CI; int tap = rest / CI;
        ws[(tap*CI + c)*JP + j] = w_off[(j*CI + c)*KKN + tap];
    }
    __syncthreads();

    int p = blockIdx.x * blockDim.x + tid;
    int b = p >> 14, rem = p & (HWI-1);
    int h = rem >> 7, w = rem & (WI-1);
    const float* xb = x + b*CI*HWI;

    u64 acc[9];
    #pragma unroll
    for (int q = 0; q < 9; q++)
        acc[q] = pack2(__ldg(&b_off[2*q]), __ldg(&b_off[2*q+1]));

    for (int tap = 0; tap < KKN; tap++) {
        int ky = tap / 3, kx = tap % 3;
        int y = h - 1 + ky, xx = w - 1 + kx;
        bool v = (y >= 0) & (y < HI) & (xx >= 0) & (xx < WI);
        int idx = y*WI + xx;
        const float* wrow = ws + tap*CI*JP;
        for (int c = 0; c < CI; c++) {
            float a = v ? __ldg(xb + c*HWI + idx) : 0.f;
            u64 a2 = pack2(a, a);
            const ulonglong2* w4 = (const ulonglong2*)(wrow + c*JP);
            #pragma unroll
            for (int q = 0; q < 4; q++) {
                ulonglong2 wv = w4[q];
                ffma2(acc[2*q+0], a2, wv.x);
                ffma2(acc[2*q+1], a2, wv.y);
            }
            u64 w8 = *(const u64*)(wrow + c*JP + 16);
            ffma2(acc[8], a2, w8);
        }
    }
    #pragma unroll
    for (int q = 0; q < 9; q++) {
        float2 vv = unpack2(acc[q]);
        g_off[(b*JO + 2*q+0)*HWI + rem] = vv.x;
        g_off[(b*JO + 2*q+1)*HWI + rem] = vv.y;
    }
}

// ---------------------------------------------------------------------------
// Kernel 2: per-tap im2col into smem + register-blocked GEMM.
// Block = 128 threads = one image row (128 px). Smem = S[c][128] only (32 KB).
// Weights read per-c as uniform LDG.128 from pre-transposed g_wt (L1-resident).
// Thread GEMM tile: 8 o  x  8 px (two quads at 4*(tid&15) + 64j).
// ---------------------------------------------------------------------------
__global__ __launch_bounds__(128, 4)
void deform_main_kernel(const float* __restrict__ x,
                        float* __restrict__ out) {
    __shared__ __align__(16) float S[CI*TPX];   // 32 KB

    int tid = threadIdx.x;
    int blk = blockIdx.x;
    int b = blk >> 7;
    int h = blk & 127;
    int rowoff = h * WI;
    const float* xb = x + b*CI*HWI;

    int w = tid;
    const float* offp = g_off + b*JO*HWI + rowoff + w;

    int o0 = (tid >> 4) * 8;   // 8 output channels
    int qb = tid & 15;         // quad base: px 4*qb + 64*j

    u64 acc[8][4];             // [o][j*2 + half]
    #pragma unroll
    for (int o = 0; o < 8; o++)
        #pragma unroll
        for (int q = 0; q < 4; q++) acc[o][q] = 0ULL;

    for (int kk = 0; kk < KKN; kk++) {
        __syncthreads();   // previous GEMM done reading S

        // bilinear setup for own pixel
        float dy = __ldg(offp + (2*kk + 0)*HWI);
        float dx = __ldg(offp + (2*kk + 1)*HWI);
        float py = (float)(h - 1 + kk / 3) + dy;
        float px = (float)(w - 1 + kk % 3) + dx;
        float y0f = floorf(py), x0f = floorf(px);
        float fy = py - y0f, fx = px - x0f;
        int y0 = (int)y0f, x0 = (int)x0f;
        int y1 = y0 + 1,   x1 = x0 + 1;
        float vy0 = (y0 >= 0 && y0 < HI) ? 1.f : 0.f;
        float vy1 = (y1 >= 0 && y1 < HI) ? 1.f : 0.f;
        float vx0 = (x0 >= 0 && x0 < WI) ? 1.f : 0.f;
        float vx1 = (x1 >= 0 && x1 < WI) ? 1.f : 0.f;
        float w00 = (1.f - fy) * (1.f - fx) * vy0 * vx0;
        float w01 = (1.f - fy) * fx         * vy0 * vx1;
        float w10 = fy         * (1.f - fx) * vy1 * vx0;
        float w11 = fy         * fx         * vy1 * vx1;
        int y0c = min(max(y0, 0), HI-1), y1c = min(max(y1, 0), HI-1);
        int x0c = min(max(x0, 0), WI-1), x1c = min(max(x1, 0), WI-1);
        int i00 = y0c*WI + x0c, i01 = y0c*WI + x1c;
        int i10 = y1c*WI + x0c, i11 = y1c*WI + x1c;

        // sample all channels -> S[c][tid]
        #pragma unroll 4
        for (int c = 0; c < CI; c++) {
            const float* xc = xb + c*HWI;
            float s = w00*__ldg(xc + i00) + w01*__ldg(xc + i01)
                    + w10*__ldg(xc + i10) + w11*__ldg(xc + i11);
            S[c*TPX + tid] = s;
        }
        __syncthreads();

        // GEMM: acc[8o][8px] += W[o][c] * S[c][px]
        const float* wk = g_wt + kk*CI*CO + o0;
        #pragma unroll 2
        for (int c = 0; c < CI; c++) {
            const float* wr = wk + (c << 6);
            float4 wa = __ldg((const float4*)(wr));
            float4 wb = __ldg((const float4*)(wr + 4));
            u64 w2[8];
            w2[0] = pack2(wa.x, wa.x); w2[1] = pack2(wa.y, wa.y);
            w2[2] = pack2(wa.z, wa.z); w2[3] = pack2(wa.w, wa.w);
            w2[4] = pack2(wb.x, wb.x); w2[5] = pack2(wb.y, wb.y);
            w2[6] = pack2(wb.z, wb.z); w2[7] = pack2(wb.w, wb.w);
            const float* srow = S + c*TPX + 4*qb;
            ulonglong2 sj0 = *(const ulonglong2*)(srow);
            ulonglong2 sj1 = *(const ulonglong2*)(srow + 64);
            #pragma unroll
            for (int o = 0; o < 8; o++) {
                ffma2(acc[o][0], sj0.x, w2[o]);
                ffma2(acc[o][1], sj0.y, w2[o]);
                ffma2(acc[o][2], sj1.x, w2[o]);
                ffma2(acc[o][3], sj1.y, w2[o]);
            }
        }
    }

    // write out: thread's px quads at 4*qb + 64*j
    #pragma unroll
    for (int o = 0; o < 8; o++) {
        float* orow = out + (b*CO + o0 + o)*HWI + rowoff;
        #pragma unroll
        for (int j = 0; j < 2; j++) {
            float2 v0 = unpack2(acc[o][2*j+0]);
            float2 v1 = unpack2(acc[o][2*j+1]);
            float4 v = make_float4(v0.x, v0.y, v1.x, v1.y);
            *(float4*)(orow + 4*qb + 64*j) = v;
        }
    }
}

// ---------------------------------------------------------------------------
// Launch
// Inputs: x (4*64*128*128), w_off (18*64*9), b_off (18), w_def (64*64*9)
// Output: (4, 64, 128, 128) fp32
// ---------------------------------------------------------------------------
extern "C" void kernel_launch(void* const* d_in, const int* in_sizes, int n_in,
                              void* d_out, int out_size) {
    const float* x     = (const float*)d_in[0];
    const float* w_off = (const float*)d_in[1];
    const float* b_off = (const float*)d_in[2];
    const float* w_def = (const float*)d_in[3];
    float* out = (float*)d_out;

    const int total_px = BI*HWI;  // 65536

    transpose_wdef_kernel<<<(KKN*CI*CO + 255)/256, 256>>>(w_def);
    offset_conv_kernel<<<total_px/256, 256>>>(x, w_off, b_off);
    deform_main_kernel<<<total_px/TPX, TPX>>>(x, out);
}